// round 4
// baseline (speedup 1.0000x reference)
#include <cuda_runtime.h>
#include <float.h>

// VectorQuantizer, bit-emulating the reference's fp32 numerics:
//   x2_r  = sequential fold_d fadd(acc, fmul(x,x))          (XLA reduce, no fma)
//   e2_k  = sequential fold_d fadd(acc, fmul(e,e))
//   dot   = sequential fold_d fmaf(x, e, acc)               (Eigen gebp, fused)
//   d_k   = fsub(fadd(x2, e2_k), 2*dot_k)   (2*dot exact)
//   idx   = first argmin (ascending tie-break)
//   out   = fadd(x, fsub(q, x))             (straight-through, rounded like ref)
//   loss  = 1.25 * mean(fmul(fsub(q,x),fsub(q,x)))

constexpr int D       = 256;
constexpr int D4      = D / 4;
constexpr int K       = 1024;
constexpr int BM      = 64;
constexpr int BN      = 64;
constexpr int TM      = 4;
constexpr int TN      = 4;
constexpr int THREADS = 256;
constexpr int PITCH4  = D4 + 1;

constexpr int SMEM_BYTES = 2 * BM * PITCH4 * 16;

__device__ float g_e2[K];
__device__ float g_loss;

// --- per-code squared norms, STRICTLY sequential over d, + zero loss -------
__global__ void prep_kernel(const float* __restrict__ emb) {
    int k = blockIdx.x * blockDim.x + threadIdx.x;   // one code per thread
    if (k < K) {
        const float4* e4 = reinterpret_cast<const float4*>(emb);
        float acc = 0.0f;
        #pragma unroll 8
        for (int d = 0; d < D4; ++d) {
            float4 v = e4[(size_t)k * D4 + d];
            acc = __fadd_rn(acc, __fmul_rn(v.x, v.x));
            acc = __fadd_rn(acc, __fmul_rn(v.y, v.y));
            acc = __fadd_rn(acc, __fmul_rn(v.z, v.z));
            acc = __fadd_rn(acc, __fmul_rn(v.w, v.w));
        }
        g_e2[k] = acc;
    }
    if (k == 0) g_loss = 0.0f;
}

// --- main fused kernel ------------------------------------------------------
extern __shared__ float smem_raw[];

__global__ __launch_bounds__(THREADS, 1)
void vq_kernel(const float* __restrict__ x, const float* __restrict__ emb,
               float* __restrict__ out) {
    float4* xs = reinterpret_cast<float4*>(smem_raw);        // [BM][PITCH4]
    float4* es = xs + BM * PITCH4;                           // [BN][PITCH4]

    __shared__ float x2s[BM];
    __shared__ float red_s[BM][16];
    __shared__ int   red_k[BM][16];
    __shared__ int   fin_k[BM];
    __shared__ float red_l[THREADS];

    const int tid = threadIdx.x;
    const int tx  = tid & 15;
    const int ty  = tid >> 4;
    const int rowBase = blockIdx.x * BM;

    const float4* x4 = reinterpret_cast<const float4*>(x);
    const float4* e4 = reinterpret_cast<const float4*>(emb);

    // load x tile (coalesced float4)
    #pragma unroll
    for (int i = 0; i < (BM * D4) / THREADS; ++i) {
        int t = tid + i * THREADS;
        int r = t >> 6, c = t & 63;
        xs[r * PITCH4 + c] = x4[(size_t)(rowBase + r) * D4 + c];
    }
    __syncthreads();

    // x2 per row: strictly sequential fadd(fmul) over d, ascending
    if (tid < BM) {
        float acc = 0.0f;
        #pragma unroll 8
        for (int d = 0; d < D4; ++d) {
            float4 v = xs[tid * PITCH4 + d];
            acc = __fadd_rn(acc, __fmul_rn(v.x, v.x));
            acc = __fadd_rn(acc, __fmul_rn(v.y, v.y));
            acc = __fadd_rn(acc, __fmul_rn(v.z, v.z));
            acc = __fadd_rn(acc, __fmul_rn(v.w, v.w));
        }
        x2s[tid] = acc;
    }

    float best[TM];
    int   bestk[TM];
    #pragma unroll
    for (int i = 0; i < TM; ++i) { best[i] = FLT_MAX; bestk[i] = 0; }

    const int r0 = ty * TM;
    const int c0 = tx * TN;

    for (int nt = 0; nt < K / BN; ++nt) {
        __syncthreads();   // fences x2s writes (iter 0) and prior es reads
        #pragma unroll
        for (int i = 0; i < (BN * D4) / THREADS; ++i) {
            int t = tid + i * THREADS;
            int r = t >> 6, c = t & 63;
            es[r * PITCH4 + c] = e4[(size_t)(nt * BN + r) * D4 + c];
        }
        __syncthreads();

        float acc[TM][TN];
        #pragma unroll
        for (int i = 0; i < TM; ++i)
            #pragma unroll
            for (int j = 0; j < TN; ++j) acc[i][j] = 0.f;

        // dot: sequential fused-FMA chain in ascending k per output
        #pragma unroll 4
        for (int d = 0; d < D4; ++d) {
            float4 a[TM], b[TN];
            #pragma unroll
            for (int i = 0; i < TM; ++i) a[i] = xs[(r0 + i) * PITCH4 + d];
            #pragma unroll
            for (int j = 0; j < TN; ++j) b[j] = es[(c0 + j) * PITCH4 + d];
            #pragma unroll
            for (int i = 0; i < TM; ++i)
                #pragma unroll
                for (int j = 0; j < TN; ++j) {
                    float s = acc[i][j];
                    s = __fmaf_rn(a[i].x, b[j].x, s);
                    s = __fmaf_rn(a[i].y, b[j].y, s);
                    s = __fmaf_rn(a[i].z, b[j].z, s);
                    s = __fmaf_rn(a[i].w, b[j].w, s);
                    acc[i][j] = s;
                }
        }

        // d_k = fsub(fadd(x2, e2_k), 2*dot_k); running first-min argmin
        #pragma unroll
        for (int j = 0; j < TN; ++j) {
            int code = nt * BN + c0 + j;
            float e2 = g_e2[code];
            #pragma unroll
            for (int i = 0; i < TM; ++i) {
                float A = __fadd_rn(x2s[r0 + i], e2);
                float dd = __fsub_rn(A, 2.0f * acc[i][j]);
                if (dd < best[i]) { best[i] = dd; bestk[i] = code; }
            }
        }
    }

    // cross-thread argmin per row (tie -> smallest k, matches first-min)
    #pragma unroll
    for (int i = 0; i < TM; ++i) {
        red_s[r0 + i][tx] = best[i];
        red_k[r0 + i][tx] = bestk[i];
    }
    __syncthreads();
    if (tid < BM) {
        float bs = red_s[tid][0];
        int   bk = red_k[tid][0];
        #pragma unroll
        for (int j = 1; j < 16; ++j) {
            float s = red_s[tid][j];
            int  kk = red_k[tid][j];
            if (s < bs || (s == bs && kk < bk)) { bs = s; bk = kk; }
        }
        fin_k[tid] = bk;
    }
    __syncthreads();

    // epilogue: gather winning rows, write fl(x + fl(q - x)), accumulate loss
    float lsum = 0.f;
    float4* out4 = reinterpret_cast<float4*>(out);
    #pragma unroll
    for (int i = 0; i < (BM * D4) / THREADS; ++i) {
        int t = tid + i * THREADS;
        int r = t >> 6, c = t & 63;
        float4 q  = e4[(size_t)fin_k[r] * D4 + c];
        float4 xv = xs[r * PITCH4 + c];
        float dx = __fsub_rn(q.x, xv.x);
        float dy = __fsub_rn(q.y, xv.y);
        float dz = __fsub_rn(q.z, xv.z);
        float dw = __fsub_rn(q.w, xv.w);
        float4 o;
        o.x = __fadd_rn(xv.x, dx);
        o.y = __fadd_rn(xv.y, dy);
        o.z = __fadd_rn(xv.z, dz);
        o.w = __fadd_rn(xv.w, dw);
        out4[(size_t)(rowBase + r) * D4 + c] = o;
        lsum += __fmul_rn(dx, dx) + __fmul_rn(dy, dy)
              + __fmul_rn(dz, dz) + __fmul_rn(dw, dw);
    }
    red_l[tid] = lsum;
    __syncthreads();
    if (tid < 128) red_l[tid] += red_l[tid + 128];
    __syncthreads();
    if (tid < 64)  red_l[tid] += red_l[tid + 64];
    __syncthreads();
    if (tid < 32) {
        float r = red_l[tid] + red_l[tid + 32];
        #pragma unroll
        for (int o = 16; o > 0; o >>= 1) r += __shfl_down_sync(0xffffffffu, r, o);
        if (tid == 0) atomicAdd(&g_loss, r);
    }
}

// --- finalize loss ----------------------------------------------------------
__global__ void fin_kernel(float* __restrict__ out, int nd, int out_size) {
    if (out_size > nd) {
        float m = g_loss / (float)nd;          // nd = 2^22 -> exact scaling
        out[nd] = __fmul_rn(1.25f, m);
    }
}

extern "C" void kernel_launch(void* const* d_in, const int* in_sizes, int n_in,
                              void* d_out, int out_size) {
    const float* x   = (const float*)d_in[0];
    const float* emb = (const float*)d_in[1];
    float* out = (float*)d_out;

    const int ND = in_sizes[0];      // 4194304
    const int N  = ND / D;           // 65536

    cudaFuncSetAttribute(vq_kernel, cudaFuncAttributeMaxDynamicSharedMemorySize,
                         SMEM_BYTES);

    prep_kernel<<<K / 256, 256>>>(emb);
    vq_kernel<<<N / BM, THREADS, SMEM_BYTES>>>(x, emb, out);
    fin_kernel<<<1, 1>>>(out, ND, out_size);
}

// round 5
// speedup vs baseline: 2.6160x; 2.6160x over previous
#include <cuda_runtime.h>
#include <float.h>

// VectorQuantizer, bit-emulating the reference fp32 numerics (validated R3):
//   x2_r = sequential fold_d fadd(acc, fmul(x,x))
//   e2_k = sequential fold_d fadd(acc, fmul(e,e))
//   dot  = sequential fold_d fmaf(x, e, acc)      (one chain per output)
//   d_k  = fsub(fadd(x2, e2_k), 2*dot_k)
//   idx  = first argmin (ascending tie-break)
//   out  = fadd(x, fsub(q, x));  loss = 1.25 * mean(fsub(q,x)^2)
//
// R4: register tile 4x8 (BM=64, BN=128) -> 128 FFMA per 12 LDS.128, FMA-bound.

constexpr int D       = 256;
constexpr int D4      = D / 4;
constexpr int K       = 1024;
constexpr int BM      = 64;
constexpr int BN      = 128;
constexpr int TM      = 4;
constexpr int TN      = 8;
constexpr int THREADS = 256;       // 16 x 16
constexpr int PITCH4  = D4 + 1;    // 65 float4; b-load tx stride = 260 floats = 4 mod 32 banks

constexpr int SMEM_BYTES = (BM + BN) * PITCH4 * 16;   // 199680 B

__device__ float g_e2[K];
__device__ float g_loss;

// --- per-code squared norms (coalesced load, sequential fold) + zero loss ---
__global__ void prep_kernel(const float* __restrict__ emb) {
    // 8 warps/block, one code per warp; 128 blocks
    __shared__ float4 row[8][D4];
    int wid = threadIdx.x >> 5, lid = threadIdx.x & 31;
    int k = blockIdx.x * 8 + wid;
    const float4* e4 = reinterpret_cast<const float4*>(emb);
    row[wid][lid]      = e4[(size_t)k * D4 + lid];
    row[wid][lid + 32] = e4[(size_t)k * D4 + lid + 32];
    __syncwarp();
    if (lid == 0) {
        float acc = 0.0f;
        #pragma unroll 8
        for (int d = 0; d < D4; ++d) {
            float4 v = row[wid][d];
            acc = __fadd_rn(acc, __fmul_rn(v.x, v.x));
            acc = __fadd_rn(acc, __fmul_rn(v.y, v.y));
            acc = __fadd_rn(acc, __fmul_rn(v.z, v.z));
            acc = __fadd_rn(acc, __fmul_rn(v.w, v.w));
        }
        g_e2[k] = acc;
    }
    if (k == 0 && lid == 0) g_loss = 0.0f;
}

// --- main fused kernel ------------------------------------------------------
extern __shared__ float smem_raw[];

__global__ __launch_bounds__(THREADS, 1)
void vq_kernel(const float* __restrict__ x, const float* __restrict__ emb,
               float* __restrict__ out) {
    float4* xs = reinterpret_cast<float4*>(smem_raw);        // [BM][PITCH4]
    float4* es = xs + BM * PITCH4;                           // [BN][PITCH4]

    __shared__ float x2s[BM];
    __shared__ float red_s[BM][16];
    __shared__ int   red_k[BM][16];
    __shared__ int   fin_k[BM];
    __shared__ float red_l[THREADS];

    const int tid = threadIdx.x;
    const int tx  = tid & 15;          // code group: codes j*16 + tx
    const int ty  = tid >> 4;          // row group:  rows  i*16 + ty
    const int rowBase = blockIdx.x * BM;

    const float4* x4 = reinterpret_cast<const float4*>(x);
    const float4* e4 = reinterpret_cast<const float4*>(emb);

    // load x tile (coalesced float4)
    #pragma unroll
    for (int i = 0; i < (BM * D4) / THREADS; ++i) {
        int t = tid + i * THREADS;
        int r = t >> 6, c = t & 63;
        xs[r * PITCH4 + c] = x4[(size_t)(rowBase + r) * D4 + c];
    }
    __syncthreads();

    // x2 per row: strictly sequential fadd(fmul), ascending d
    if (tid < BM) {
        float acc = 0.0f;
        #pragma unroll 8
        for (int d = 0; d < D4; ++d) {
            float4 v = xs[tid * PITCH4 + d];
            acc = __fadd_rn(acc, __fmul_rn(v.x, v.x));
            acc = __fadd_rn(acc, __fmul_rn(v.y, v.y));
            acc = __fadd_rn(acc, __fmul_rn(v.z, v.z));
            acc = __fadd_rn(acc, __fmul_rn(v.w, v.w));
        }
        x2s[tid] = acc;
    }

    float best[TM];
    int   bestk[TM];
    #pragma unroll
    for (int i = 0; i < TM; ++i) { best[i] = FLT_MAX; bestk[i] = 0; }

    for (int nt = 0; nt < K / BN; ++nt) {
        __syncthreads();   // fences x2s (iter 0) and prior es reads
        #pragma unroll
        for (int i = 0; i < (BN * D4) / THREADS; ++i) {
            int t = tid + i * THREADS;
            int r = t >> 6, c = t & 63;
            es[r * PITCH4 + c] = e4[(size_t)(nt * BN + r) * D4 + c];
        }
        __syncthreads();

        float acc[TM][TN];
        #pragma unroll
        for (int i = 0; i < TM; ++i)
            #pragma unroll
            for (int j = 0; j < TN; ++j) acc[i][j] = 0.f;

        // dot: one sequential fused-FMA chain per output, ascending d
        #pragma unroll 4
        for (int d = 0; d < D4; ++d) {
            float4 a[TM], b[TN];
            #pragma unroll
            for (int i = 0; i < TM; ++i) a[i] = xs[(i * 16 + ty) * PITCH4 + d];
            #pragma unroll
            for (int j = 0; j < TN; ++j) b[j] = es[(j * 16 + tx) * PITCH4 + d];
            #pragma unroll
            for (int i = 0; i < TM; ++i)
                #pragma unroll
                for (int j = 0; j < TN; ++j) {
                    float s = acc[i][j];
                    s = __fmaf_rn(a[i].x, b[j].x, s);
                    s = __fmaf_rn(a[i].y, b[j].y, s);
                    s = __fmaf_rn(a[i].z, b[j].z, s);
                    s = __fmaf_rn(a[i].w, b[j].w, s);
                    acc[i][j] = s;
                }
        }

        // d_k = fsub(fadd(x2, e2_k), 2*dot); running first-min (j ascending
        // => code ascending per thread, strict '<' keeps first minimum)
        #pragma unroll
        for (int j = 0; j < TN; ++j) {
            int code = nt * BN + j * 16 + tx;
            float e2 = g_e2[code];
            #pragma unroll
            for (int i = 0; i < TM; ++i) {
                float A  = __fadd_rn(x2s[i * 16 + ty], e2);
                float dd = __fsub_rn(A, 2.0f * acc[i][j]);
                if (dd < best[i]) { best[i] = dd; bestk[i] = code; }
            }
        }
    }

    // cross-thread argmin per row (tie -> smallest k)
    #pragma unroll
    for (int i = 0; i < TM; ++i) {
        red_s[i * 16 + ty][tx] = best[i];
        red_k[i * 16 + ty][tx] = bestk[i];
    }
    __syncthreads();
    if (tid < BM) {
        float bs = red_s[tid][0];
        int   bk = red_k[tid][0];
        #pragma unroll
        for (int j = 1; j < 16; ++j) {
            float s = red_s[tid][j];
            int  kk = red_k[tid][j];
            if (s < bs || (s == bs && kk < bk)) { bs = s; bk = kk; }
        }
        fin_k[tid] = bk;
    }
    __syncthreads();

    // epilogue: gather winners, write fl(x + fl(q - x)), accumulate loss
    float lsum = 0.f;
    float4* out4 = reinterpret_cast<float4*>(out);
    #pragma unroll
    for (int i = 0; i < (BM * D4) / THREADS; ++i) {
        int t = tid + i * THREADS;
        int r = t >> 6, c = t & 63;
        float4 q  = e4[(size_t)fin_k[r] * D4 + c];
        float4 xv = xs[r * PITCH4 + c];
        float dx = __fsub_rn(q.x, xv.x);
        float dy = __fsub_rn(q.y, xv.y);
        float dz = __fsub_rn(q.z, xv.z);
        float dw = __fsub_rn(q.w, xv.w);
        float4 o;
        o.x = __fadd_rn(xv.x, dx);
        o.y = __fadd_rn(xv.y, dy);
        o.z = __fadd_rn(xv.z, dz);
        o.w = __fadd_rn(xv.w, dw);
        out4[(size_t)(rowBase + r) * D4 + c] = o;
        lsum += __fmul_rn(dx, dx) + __fmul_rn(dy, dy)
              + __fmul_rn(dz, dz) + __fmul_rn(dw, dw);
    }
    red_l[tid] = lsum;
    __syncthreads();
    if (tid < 128) red_l[tid] += red_l[tid + 128];
    __syncthreads();
    if (tid < 64)  red_l[tid] += red_l[tid + 64];
    __syncthreads();
    if (tid < 32) {
        float r = red_l[tid] + red_l[tid + 32];
        #pragma unroll
        for (int o = 16; o > 0; o >>= 1) r += __shfl_down_sync(0xffffffffu, r, o);
        if (tid == 0) atomicAdd(&g_loss, r);
    }
}

// --- finalize loss ----------------------------------------------------------
__global__ void fin_kernel(float* __restrict__ out, int nd, int out_size) {
    if (out_size > nd) {
        float m = g_loss / (float)nd;          // nd = 2^22 -> exact
        out[nd] = __fmul_rn(1.25f, m);
    }
}

extern "C" void kernel_launch(void* const* d_in, const int* in_sizes, int n_in,
                              void* d_out, int out_size) {
    const float* x   = (const float*)d_in[0];
    const float* emb = (const float*)d_in[1];
    float* out = (float*)d_out;

    const int ND = in_sizes[0];      // 4194304
    const int N  = ND / D;           // 65536

    cudaFuncSetAttribute(vq_kernel, cudaFuncAttributeMaxDynamicSharedMemorySize,
                         SMEM_BYTES);

    prep_kernel<<<K / 8, 256>>>(emb);
    vq_kernel<<<N / BM, THREADS, SMEM_BYTES>>>(x, emb, out);
    fin_kernel<<<1, 1>>>(out, ND, out_size);
}